// round 1
// baseline (speedup 1.0000x reference)
#include <cuda_runtime.h>
#include <math.h>

#define HH 64
#define WW 64
#define CC 256
#define BATCH 16
#define NHEAD 8
#define HDIM 32
#define WSZ 8
#define NPIX 4096         // HH*WW
#define C3 768            // 3*CC

// Scratch (allocation-free rule: __device__ globals)
__device__ float g_qkv[(size_t)BATCH * C3 * NPIX];   // [b][3C][pix]
__device__ float g_attn[(size_t)BATCH * CC * NPIX];  // [b][C][pix]

// ---------------------------------------------------------------------------
// GEMM: Y[b, m, p] = sum_k Wt[m, k] * X[b, k, p];  K = 256, N = NPIX = 4096
// Tiles: BM=BN=128, BK=16, 256 threads, 8x8 per-thread register tile.
// grid = (N/128, M/128, BATCH)
// ---------------------------------------------------------------------------
__global__ __launch_bounds__(256) void gemm_k256(
    const float* __restrict__ Wt, const float* __restrict__ X,
    float* __restrict__ Y, long xStrideB, long yStrideB)
{
    __shared__ __align__(16) float As[16][128];
    __shared__ __align__(16) float Bs[16][128];

    const int tid = threadIdx.x;
    const int bn  = blockIdx.x;     // pixel tile
    const int bm  = blockIdx.y;     // output-channel tile
    const int b   = blockIdx.z;

    const float* Xb = X + (long)b * xStrideB;
    float*       Yb = Y + (long)b * yStrideB;

    const int ty = tid >> 4;        // 0..15
    const int tx = tid & 15;        // 0..15

    // A-load mapping: 128 rows x 16 k, 2 float4 per thread
    const int ar = tid >> 2;             // 0..63
    const int ak = (tid & 3) * 4;        // 0,4,8,12
    // B-load mapping: 16 k x 128 cols, 2 float4 per thread
    const int bk = tid >> 5;             // 0..7
    const int bc = (tid & 31) * 4;       // 0..124

    float acc[8][8];
#pragma unroll
    for (int i = 0; i < 8; i++)
#pragma unroll
        for (int j = 0; j < 8; j++) acc[i][j] = 0.0f;

    for (int k0 = 0; k0 < 256; k0 += 16) {
#pragma unroll
        for (int m = 0; m < 2; m++) {
            const int row = bm * 128 + ar + m * 64;
            float4 w4 = *(const float4*)(Wt + (long)row * 256 + k0 + ak);
            As[ak + 0][ar + m * 64] = w4.x;
            As[ak + 1][ar + m * 64] = w4.y;
            As[ak + 2][ar + m * 64] = w4.z;
            As[ak + 3][ar + m * 64] = w4.w;
        }
#pragma unroll
        for (int m = 0; m < 2; m++) {
            const int kk = bk + m * 8;
            float4 x4 = *(const float4*)(Xb + (long)(k0 + kk) * NPIX + bn * 128 + bc);
            *(float4*)&Bs[kk][bc] = x4;
        }
        __syncthreads();

#pragma unroll
        for (int kk = 0; kk < 16; kk++) {
            float a[8], bb[8];
            *(float4*)(a)      = *(const float4*)&As[kk][ty * 8];
            *(float4*)(a + 4)  = *(const float4*)&As[kk][ty * 8 + 4];
            *(float4*)(bb)     = *(const float4*)&Bs[kk][tx * 8];
            *(float4*)(bb + 4) = *(const float4*)&Bs[kk][tx * 8 + 4];
#pragma unroll
            for (int i = 0; i < 8; i++)
#pragma unroll
                for (int j = 0; j < 8; j++)
                    acc[i][j] += a[i] * bb[j];
        }
        __syncthreads();
    }

#pragma unroll
    for (int i = 0; i < 8; i++) {
        const int row = bm * 128 + ty * 8 + i;
        float* yr = Yb + (long)row * NPIX + bn * 128 + tx * 8;
        *(float4*)(yr)     = make_float4(acc[i][0], acc[i][1], acc[i][2], acc[i][3]);
        *(float4*)(yr + 4) = make_float4(acc[i][4], acc[i][5], acc[i][6], acc[i][7]);
    }
}

// ---------------------------------------------------------------------------
// Windowed attention, one block per (head, window, batch); 64 threads = tokens.
// Roll folded into gather/scatter coordinate g.
// grid = (NHEAD, 64 windows, BATCH), block = 64
// ---------------------------------------------------------------------------
__global__ __launch_bounds__(64) void attn_kernel(
    const float* __restrict__ qkv, float* __restrict__ attn,
    const int* __restrict__ shift_ptr)
{
    __shared__ __align__(16) float ks[64][36];  // padded to 36 (16B aligned rows)
    __shared__ __align__(16) float vs[64][36];

    const int t    = threadIdx.x;         // token 0..63
    const int head = blockIdx.x;
    const int win  = blockIdx.y;
    const int wy   = win >> 3, wx = win & 7;
    const int b    = blockIdx.z;

    const int s  = (*shift_ptr != 0) ? (WSZ / 2) : 0;
    const int ti = t >> 3, tj = t & 7;
    const int gh = (wy * 8 + ti + s) & 63;
    const int gw = (wx * 8 + tj + s) & 63;
    const int g  = gh * 64 + gw;

    const long baseq = ((long)b * C3 + head * HDIM) * NPIX;
    const long basek = baseq + (long)CC * NPIX;
    const long basev = baseq + (long)(2 * CC) * NPIX;

    float q[32];
#pragma unroll
    for (int d = 0; d < 32; d++) q[d] = qkv[baseq + (long)d * NPIX + g];
#pragma unroll
    for (int d = 0; d < 32; d++) ks[t][d] = qkv[basek + (long)d * NPIX + g];
#pragma unroll
    for (int d = 0; d < 32; d++) vs[t][d] = qkv[basev + (long)d * NPIX + g];
    __syncthreads();

    const float scale = 0.17677669529663688f;  // 1/sqrt(32)

    float sc[64];
#pragma unroll
    for (int j = 0; j < 64; j++) {
        float dotv = 0.0f;
#pragma unroll
        for (int d4 = 0; d4 < 8; d4++) {
            float4 kv = *(const float4*)&ks[j][d4 * 4];
            dotv += q[d4 * 4 + 0] * kv.x;
            dotv += q[d4 * 4 + 1] * kv.y;
            dotv += q[d4 * 4 + 2] * kv.z;
            dotv += q[d4 * 4 + 3] * kv.w;
        }
        sc[j] = dotv * scale;
    }

    float mx = sc[0];
#pragma unroll
    for (int j = 1; j < 64; j++) mx = fmaxf(mx, sc[j]);
    float sum = 0.0f;
#pragma unroll
    for (int j = 0; j < 64; j++) { sc[j] = __expf(sc[j] - mx); sum += sc[j]; }
    const float inv = 1.0f / sum;

    float o[32];
#pragma unroll
    for (int d = 0; d < 32; d++) o[d] = 0.0f;
#pragma unroll
    for (int j = 0; j < 64; j++) {
        const float p = sc[j] * inv;
#pragma unroll
        for (int d4 = 0; d4 < 8; d4++) {
            float4 vv = *(const float4*)&vs[j][d4 * 4];
            o[d4 * 4 + 0] += p * vv.x;
            o[d4 * 4 + 1] += p * vv.y;
            o[d4 * 4 + 2] += p * vv.z;
            o[d4 * 4 + 3] += p * vv.w;
        }
    }

    const long baseo = ((long)b * CC + head * HDIM) * NPIX;
#pragma unroll
    for (int d = 0; d < 32; d++)
        attn[baseo + (long)d * NPIX + g] = o[d];
}

// ---------------------------------------------------------------------------
extern "C" void kernel_launch(void* const* d_in, const int* in_sizes, int n_in,
                              void* d_out, int out_size)
{
    (void)in_sizes; (void)n_in; (void)out_size;
    const float* x      = (const float*)d_in[0];
    const float* w_qkv  = (const float*)d_in[1];
    const float* w_proj = (const float*)d_in[2];
    const int*   shift  = (const int*)d_in[3];
    float*       out    = (float*)d_out;

    float *qkv_ptr, *attn_ptr;
    cudaGetSymbolAddress((void**)&qkv_ptr,  g_qkv);
    cudaGetSymbolAddress((void**)&attn_ptr, g_attn);

    // K1: qkv = W_qkv @ X   (M=768, N=4096, K=256) per batch
    gemm_k256<<<dim3(NPIX / 128, C3 / 128, BATCH), 256>>>(
        w_qkv, x, qkv_ptr, (long)CC * NPIX, (long)C3 * NPIX);

    // K2: windowed attention with roll folded into gather/scatter
    attn_kernel<<<dim3(NHEAD, 64, BATCH), 64>>>(qkv_ptr, attn_ptr, shift);

    // K3: out = W_proj @ attn  (M=256, N=4096, K=256) per batch
    gemm_k256<<<dim3(NPIX / 128, CC / 128, BATCH), 256>>>(
        w_proj, attn_ptr, out, (long)CC * NPIX, (long)CC * NPIX);
}

// round 3
// speedup vs baseline: 1.1663x; 1.1663x over previous
#include <cuda_runtime.h>
#include <cuda_bf16.h>
#include <stdint.h>

#define CC 256
#define C3 768
#define NPIX 4096
#define BATCH 16
#define NHEAD 8
#define WSZ 8
#define KP 768              // tripled K for split-bf16 GEMM
#define NCHUNK 12           // 768 / 64
#define PITCH 144           // smem row pitch in bytes (64 bf16 = 128B + 16B pad)
#define ATILE (128 * PITCH) // 18432 bytes
#define STAGE_BYTES (2 * ATILE)
#define NSTAGE 2
#define DYN_SMEM (NSTAGE * STAGE_BYTES)

// ---------------- scratch (__device__ globals; no allocations allowed) -----
__device__ __align__(16) float         g_qkv[(size_t)BATCH * C3 * NPIX];  // [b][768][pix]
__device__ __align__(16) __nv_bfloat16 g_xs [(size_t)BATCH * NPIX * KP];  // X split [b][pix][768]
__device__ __align__(16) __nv_bfloat16 g_as [(size_t)BATCH * NPIX * KP];  // attn split
__device__ __align__(16) __nv_bfloat16 g_wqs[(size_t)C3 * KP];            // W_qkv split
__device__ __align__(16) __nv_bfloat16 g_wps[(size_t)CC * KP];            // W_proj split

// ---------------- helpers ---------------------------------------------------
__device__ __forceinline__ uint32_t smem_u32(const void* p) {
    uint32_t a;
    asm("{ .reg .u64 t; cvta.to.shared.u64 t, %1; cvt.u32.u64 %0, t; }" : "=r"(a) : "l"(p));
    return a;
}
__device__ __forceinline__ void cp16(uint32_t d, const void* s) {
    asm volatile("cp.async.cg.shared.global [%0], [%1], 16;" :: "r"(d), "l"(s) : "memory");
}
__device__ __forceinline__ void cp_commit() {
    asm volatile("cp.async.commit_group;" ::: "memory");
}
template <int N> __device__ __forceinline__ void cp_wait() {
    asm volatile("cp.async.wait_group %0;" :: "n"(N) : "memory");
}
__device__ __forceinline__ void mma16816(float* d,
                                         uint32_t a0, uint32_t a1, uint32_t a2, uint32_t a3,
                                         uint32_t b0, uint32_t b1) {
    asm volatile(
        "mma.sync.aligned.m16n8k16.row.col.f32.bf16.bf16.f32 "
        "{%0,%1,%2,%3}, {%4,%5,%6,%7}, {%8,%9}, {%0,%1,%2,%3};"
        : "+f"(d[0]), "+f"(d[1]), "+f"(d[2]), "+f"(d[3])
        : "r"(a0), "r"(a1), "r"(a2), "r"(a3), "r"(b0), "r"(b1));
}

// ---------------------------------------------------------------------------
// Split-bf16 GEMM via mma.sync (HMMA):
//   D[b][bm*128+m][bn*128+n] = sum_{k'<768} A[m][k'] * B[b][n][k']
// A: [Mtot][768] bf16 row-major(K-contig); B: [b][4096][768] bf16 K-contig.
// grid = (32, Mtot/128, 16), block = 256 (8 warps, 2x4 warp grid, 64x32 each).
// ---------------------------------------------------------------------------
__global__ __launch_bounds__(256, 2)
void gemm_bf16(const __nv_bfloat16* __restrict__ A,
               const __nv_bfloat16* __restrict__ Bm,
               float* __restrict__ D, int Mtot)
{
    extern __shared__ __align__(16) char dsm[];

    const int tid = threadIdx.x;
    const int wid = tid >> 5;
    const int lid = tid & 31;
    const int bn = blockIdx.x, bm = blockIdx.y, b = blockIdx.z;

    const int warp_m = wid & 1;   // 0..1 -> 64-row slab
    const int warp_n = wid >> 1;  // 0..3 -> 32-col slab
    const uint32_t g = lid >> 2, t = lid & 3;

    const uint32_t sbase = smem_u32(dsm);

    // fill mapping: thread -> row r = tid>>1 (0..127), 64B half h = tid&1
    const int r = tid >> 1, h = tid & 1;
    const char* Ag = (const char*)A + (size_t)(bm * 128 + r) * 1536 + (size_t)h * 64;
    const char* Bg = (const char*)Bm
        + ((size_t)b * NPIX + (size_t)bn * 128 + (size_t)r) * 1536 + (size_t)h * 64;
    const uint32_t sArow = (uint32_t)r * PITCH + (uint32_t)h * 64;

    auto fill = [&](int c, int s) {
        const uint32_t sa = sbase + (uint32_t)s * STAGE_BYTES;
        const uint32_t sb = sa + ATILE;
        const char* ag = Ag + (size_t)c * 128;
        const char* bg = Bg + (size_t)c * 128;
#pragma unroll
        for (int j = 0; j < 4; j++) {
            cp16(sa + sArow + j * 16, ag + j * 16);
            cp16(sb + sArow + j * 16, bg + j * 16);
        }
        cp_commit();
    };

    fill(0, 0);
    fill(1, 1);

    float acc[4][4][4];
#pragma unroll
    for (int mi = 0; mi < 4; mi++)
#pragma unroll
        for (int ni = 0; ni < 4; ni++)
#pragma unroll
            for (int e = 0; e < 4; e++) acc[mi][ni][e] = 0.0f;

    // per-warp smem fragment bases
    const uint32_t pA0 = sbase + (uint32_t)(warp_m * 64 + g) * PITCH + 4u * t;
    const uint32_t pB0 = sbase + ATILE + (uint32_t)(warp_n * 32 + g) * PITCH + 4u * t;

    for (int c = 0; c < NCHUNK; c++) {
        cp_wait<1>();
        __syncthreads();
        const uint32_t so = (uint32_t)(c & 1) * STAGE_BYTES;

#pragma unroll
        for (int ks = 0; ks < 4; ks++) {
            const uint32_t ko = 32u * ks;
            uint32_t af[4][4], bf[4][2];
#pragma unroll
            for (int mi = 0; mi < 4; mi++) {
                const uint32_t p = pA0 + so + (uint32_t)mi * (16 * PITCH) + ko;
                asm volatile("ld.shared.b32 %0, [%1];"       : "=r"(af[mi][0]) : "r"(p));
                asm volatile("ld.shared.b32 %0, [%1+1152];"  : "=r"(af[mi][1]) : "r"(p));
                asm volatile("ld.shared.b32 %0, [%1+16];"    : "=r"(af[mi][2]) : "r"(p));
                asm volatile("ld.shared.b32 %0, [%1+1168];"  : "=r"(af[mi][3]) : "r"(p));
            }
#pragma unroll
            for (int ni = 0; ni < 4; ni++) {
                const uint32_t p = pB0 + so + (uint32_t)ni * (8 * PITCH) + ko;
                asm volatile("ld.shared.b32 %0, [%1];"    : "=r"(bf[ni][0]) : "r"(p));
                asm volatile("ld.shared.b32 %0, [%1+16];" : "=r"(bf[ni][1]) : "r"(p));
            }
#pragma unroll
            for (int mi = 0; mi < 4; mi++)
#pragma unroll
                for (int ni = 0; ni < 4; ni++)
                    mma16816(acc[mi][ni], af[mi][0], af[mi][1], af[mi][2], af[mi][3],
                             bf[ni][0], bf[ni][1]);
        }
        __syncthreads();
        if (c + 2 < NCHUNK) fill(c + 2, c & 1);
    }

    // epilogue: direct float2 stores (4 lanes per row -> 32B contiguous)
    const int row_base = bm * 128 + warp_m * 64 + (int)g;
    const int col_base = bn * 128 + warp_n * 32 + 2 * (int)t;
    float* Db = D + (size_t)b * Mtot * NPIX;
#pragma unroll
    for (int mi = 0; mi < 4; mi++) {
        const int r0 = row_base + mi * 16;
#pragma unroll
        for (int ni = 0; ni < 4; ni++) {
            const int cl = col_base + ni * 8;
            *(float2*)(Db + (size_t)r0 * NPIX + cl) =
                make_float2(acc[mi][ni][0], acc[mi][ni][1]);
            *(float2*)(Db + (size_t)(r0 + 8) * NPIX + cl) =
                make_float2(acc[mi][ni][2], acc[mi][ni][3]);
        }
    }
}

// ---------------------------------------------------------------------------
// Weight split: W[M][256] fp32 -> Ws[M][768] bf16, blocks [ah | ah | al]
// ---------------------------------------------------------------------------
__global__ void convert_w(const float* __restrict__ W, __nv_bfloat16* __restrict__ Ws, int M)
{
    int id = blockIdx.x * 256 + threadIdx.x;
    if (id >= M * 256) return;
    int m = id >> 8, k = id & 255;
    float v = W[id];
    __nv_bfloat16 hh = __float2bfloat16(v);
    __nv_bfloat16 ll = __float2bfloat16(v - __bfloat162float(hh));
    __nv_bfloat16* row = Ws + (size_t)m * KP;
    row[k] = hh; row[256 + k] = hh; row[512 + k] = ll;
}

// ---------------------------------------------------------------------------
// X transpose+split: x[b][k][p] fp32 -> Xs[b][p][768] bf16, blocks [bh | bl | bh]
// grid = (128, 8, 16), block = 256
// ---------------------------------------------------------------------------
__global__ __launch_bounds__(256) void convert_x(const float* __restrict__ X,
                                                 __nv_bfloat16* __restrict__ Xs)
{
    __shared__ float s[32][33];
    const int p0 = blockIdx.x * 32, k0 = blockIdx.y * 32, b = blockIdx.z;
    const int tx = threadIdx.x & 31, ty = threadIdx.x >> 5;
    const float* xb = X + ((size_t)b * CC + k0) * NPIX + p0;
#pragma unroll
    for (int kk = ty; kk < 32; kk += 8) s[kk][tx] = xb[(size_t)kk * NPIX + tx];
    __syncthreads();
#pragma unroll
    for (int pp = ty; pp < 32; pp += 8) {
        float v = s[tx][pp];
        __nv_bfloat16 hh = __float2bfloat16(v);
        __nv_bfloat16 ll = __float2bfloat16(v - __bfloat162float(hh));
        __nv_bfloat16* row = Xs + ((size_t)b * NPIX + p0 + pp) * KP + k0;
        row[tx] = hh; row[256 + tx] = ll; row[512 + tx] = hh;
    }
}

// ---------------------------------------------------------------------------
// Windowed attention (roll folded into gather/scatter). Output written as
// split-bf16 K-major rows for the projection GEMM: [bh | bl | bh].
// grid = (8 heads, 64 windows, 16 batch), block = 64
// ---------------------------------------------------------------------------
__global__ __launch_bounds__(64) void attn_kernel(
    const float* __restrict__ qkv, __nv_bfloat16* __restrict__ attns,
    const int* __restrict__ shift_ptr)
{
    __shared__ __align__(16) float ks[64][36];
    __shared__ __align__(16) float vs[64][36];

    const int t = threadIdx.x;
    const int head = blockIdx.x;
    const int win = blockIdx.y;
    const int wy = win >> 3, wx = win & 7;
    const int b = blockIdx.z;

    const int sft = (*shift_ptr != 0) ? (WSZ / 2) : 0;
    const int ti = t >> 3, tj = t & 7;
    const int gh = (wy * 8 + ti + sft) & 63;
    const int gw = (wx * 8 + tj + sft) & 63;
    const int g = gh * 64 + gw;

    const size_t baseq = ((size_t)b * C3 + head * 32) * NPIX;
    const size_t basek = baseq + (size_t)CC * NPIX;
    const size_t basev = baseq + (size_t)(2 * CC) * NPIX;

    float q[32];
#pragma unroll
    for (int d = 0; d < 32; d++) q[d] = qkv[baseq + (size_t)d * NPIX + g];
#pragma unroll
    for (int d = 0; d < 32; d++) ks[t][d] = qkv[basek + (size_t)d * NPIX + g];
#pragma unroll
    for (int d = 0; d < 32; d++) vs[t][d] = qkv[basev + (size_t)d * NPIX + g];
    __syncthreads();

    const float scale = 0.17677669529663688f;

    float sc[64];
#pragma unroll
    for (int j = 0; j < 64; j++) {
        float dotv = 0.0f;
#pragma unroll
        for (int d4 = 0; d4 < 8; d4++) {
            float4 kv = *(const float4*)&ks[j][d4 * 4];
            dotv += q[d4 * 4 + 0] * kv.x;
            dotv += q[d4 * 4 + 1] * kv.y;
            dotv += q[d4 * 4 + 2] * kv.z;
            dotv += q[d4 * 4 + 3] * kv.w;
        }
        sc[j] = dotv * scale;
    }

    float mx = sc[0];
#pragma unroll
    for (int j = 1; j < 64; j++) mx = fmaxf(mx, sc[j]);
    float sum = 0.0f;
#pragma unroll
    for (int j = 0; j < 64; j++) { sc[j] = __expf(sc[j] - mx); sum += sc[j]; }
    const float inv = 1.0f / sum;

    float o[32];
#pragma unroll
    for (int d = 0; d < 32; d++) o[d] = 0.0f;
#pragma unroll
    for (int j = 0; j < 64; j++) {
        const float p = sc[j] * inv;
#pragma unroll
        for (int d4 = 0; d4 < 8; d4++) {
            float4 vv = *(const float4*)&vs[j][d4 * 4];
            o[d4 * 4 + 0] += p * vv.x;
            o[d4 * 4 + 1] += p * vv.y;
            o[d4 * 4 + 2] += p * vv.z;
            o[d4 * 4 + 3] += p * vv.w;
        }
    }

    __nv_bfloat16* rp = attns + ((size_t)b * NPIX + g) * KP;
    const int c0 = head * 32;
#pragma unroll
    for (int d = 0; d < 32; d += 2) {
        float v0 = o[d], v1 = o[d + 1];
        __nv_bfloat16 h0 = __float2bfloat16(v0);
        __nv_bfloat16 l0 = __float2bfloat16(v0 - __bfloat162float(h0));
        __nv_bfloat16 h1 = __float2bfloat16(v1);
        __nv_bfloat16 l1 = __float2bfloat16(v1 - __bfloat162float(h1));
        __nv_bfloat162 hh; hh.x = h0; hh.y = h1;
        __nv_bfloat162 ll; ll.x = l0; ll.y = l1;
        *reinterpret_cast<__nv_bfloat162*>(rp + c0 + d)       = hh;
        *reinterpret_cast<__nv_bfloat162*>(rp + 256 + c0 + d) = ll;
        *reinterpret_cast<__nv_bfloat162*>(rp + 512 + c0 + d) = hh;
    }
}

// ---------------------------------------------------------------------------
extern "C" void kernel_launch(void* const* d_in, const int* in_sizes, int n_in,
                              void* d_out, int out_size)
{
    (void)in_sizes; (void)n_in; (void)out_size;
    const float* x      = (const float*)d_in[0];
    const float* w_qkv  = (const float*)d_in[1];
    const float* w_proj = (const float*)d_in[2];
    const int*   shift  = (const int*)d_in[3];
    float*       out    = (float*)d_out;

    float* qkv; __nv_bfloat16 *xs, *as, *wqs, *wps;
    cudaGetSymbolAddress((void**)&qkv, g_qkv);
    cudaGetSymbolAddress((void**)&xs,  g_xs);
    cudaGetSymbolAddress((void**)&as,  g_as);
    cudaGetSymbolAddress((void**)&wqs, g_wqs);
    cudaGetSymbolAddress((void**)&wps, g_wps);

    cudaFuncSetAttribute(gemm_bf16, cudaFuncAttributeMaxDynamicSharedMemorySize, DYN_SMEM);

    convert_w<<<C3, 256>>>(w_qkv, wqs, C3);
    convert_w<<<CC, 256>>>(w_proj, wps, CC);
    convert_x<<<dim3(128, 8, 16), 256>>>(x, xs);

    // K1: qkv = W_qkv @ X   (M=768, N=4096/batch, K'=768 split-bf16)
    gemm_bf16<<<dim3(32, 6, 16), 256, DYN_SMEM>>>(wqs, xs, qkv, C3);

    attn_kernel<<<dim3(NHEAD, 64, 16), 64>>>(qkv, as, shift);

    // K3: out = W_proj @ attn
    gemm_bf16<<<dim3(32, 2, 16), 256, DYN_SMEM>>>(wps, as, out, CC);
}